// round 6
// baseline (speedup 1.0000x reference)
#include <cuda_runtime.h>
#include <cstdint>

// Problem constants (fixed shapes: x = (8,16,96,96) f32, 24 steps)
#define N_ELEM 1179648   // 8*16*96*96
#define HALF   589824    // N_ELEM/2  (== 4 batches * 16 ch * 96*96)
#define HW     9216      // 96*96

typedef unsigned long long ull;

// ---------------- packed f32x2 helpers ----------------
__device__ __forceinline__ ull pk(float lo, float hi){ ull r; asm("mov.b64 %0,{%1,%2};":"=l"(r):"f"(lo),"f"(hi)); return r; }
__device__ __forceinline__ void upk(ull v, float&lo, float&hi){ asm("mov.b64 {%0,%1},%2;":"=f"(lo),"=f"(hi):"l"(v)); }
__device__ __forceinline__ ull fma2(ull a, ull b, ull c){ ull d; asm("fma.rn.f32x2 %0,%1,%2,%3;":"=l"(d):"l"(a),"l"(b),"l"(c)); return d; }
__device__ __forceinline__ ull add2(ull a, ull b){ ull d; asm("add.rn.f32x2 %0,%1,%2;":"=l"(d):"l"(a),"l"(b)); return d; }
__device__ __forceinline__ ull mul2(ull a, ull b){ ull d; asm("mul.rn.f32x2 %0,%1,%2;":"=l"(d):"l"(a),"l"(b)); return d; }
__device__ __forceinline__ ull sub2(ull a, ull b){ return add2(a, b ^ 0x8000000080000000ULL); }
__device__ __forceinline__ ull relu2(ull v){ float lo,hi; upk(v,lo,hi); return pk(fmaxf(lo,0.f), fmaxf(hi,0.f)); }

// ---------------- Threefry-2x32-20 (exact JAX PRNG, partitionable mode) ----------------
__host__ __device__ __forceinline__ unsigned rotl32(unsigned x, int r){
#ifdef __CUDA_ARCH__
  return __funnelshift_l(x,x,r);
#else
  return (x<<r)|(x>>(32-r));
#endif
}
__host__ __device__ __forceinline__ void tf2x32(unsigned k0,unsigned k1,unsigned x0,unsigned x1,
                                                unsigned&o0,unsigned&o1){
  unsigned k2 = k0^k1^0x1BD11BDAu;
  x0+=k0; x1+=k1;
#define TFR(a) {x0+=x1; x1=rotl32(x1,(a)); x1^=x0;}
  TFR(13)TFR(15)TFR(26)TFR(6)   x0+=k1; x1+=k2+1u;
  TFR(17)TFR(29)TFR(16)TFR(24)  x0+=k2; x1+=k0+2u;
  TFR(13)TFR(15)TFR(26)TFR(6)   x0+=k0; x1+=k1+3u;
  TFR(17)TFR(29)TFR(16)TFR(24)  x0+=k1; x1+=k2+4u;
  TFR(13)TFR(15)TFR(26)TFR(6)   x0+=k2; x1+=k0+5u;
#undef TFR
  o0=x0; o1=x1;
}
__device__ __forceinline__ unsigned rbits32(unsigned k0, unsigned k1, unsigned i){
  unsigned o0,o1; tf2x32(k0,k1, 0u, i, o0,o1); return o0^o1;
}

// ping-pong scratch: pre-mask updated state u_t
__device__ float g_U[2][N_ELEM];

// ============ common device body: perception + PRNG + MLP, from smem tile ============
// tile: [16][18][18] packed pairs of current state x_t (already alive-masked).
// Writes u_t = x + mask*update to uout.
__device__ __forceinline__ void step_core(const ull* tile, const ull* w2s, const ull* w3s,
                                          float* uout, int bp, int h, int w,
                                          int tx, int ty, unsigned k0, unsigned k1)
{
  // perception: y[3c]=identity, y[3c+1]=sobel-x, y[3c+2]=sobel-y
  ull y[48];
  const ull EIGHTH = pk(0.125f,0.125f);
  #pragma unroll
  for (int c=0;c<16;c++){
    const ull* t = tile + c*324 + (ty+1)*18 + (tx+1);
    ull a=t[-19], bb=t[-18], cc=t[-17], d=t[-1], e=t[0], f=t[1], g=t[17], hh=t[18], ii=t[19];
    y[3*c]=e;
    ull sx = sub2(f,d);
    y[3*c+1]=mul2(add2(add2(sub2(cc,a),sub2(ii,g)),add2(sx,sx)),EIGHTH);
    ull sy = sub2(hh,bb);
    y[3*c+2]=mul2(add2(add2(sub2(g,a),sub2(ii,cc)),add2(sy,sy)),EIGHTH);
  }

  // stochastic update mask (partitionable threefry): bits(i) = fold(tf(key,(0,i)))
  unsigned m0=0u, m1=0u;
  #pragma unroll 1
  for (int c=0;c<16;c++){
    unsigned i0 = (unsigned)((bp*16+c)*HW + h*96 + w);
    unsigned bits0 = rbits32(k0,k1, i0);
    unsigned bits1 = rbits32(k0,k1, i0+(unsigned)HALF);
    float u0=__uint_as_float((bits0>>9)|0x3f800000u)-1.0f;
    float u1=__uint_as_float((bits1>>9)|0x3f800000u)-1.0f;
    m0 |= (u0>0.5f)?(1u<<c):0u;
    m1 |= (u1>0.5f)?(1u<<c):0u;
  }

  // MLP: hid = relu(W2 y), out = W3 hid
  ull acc[16];
  #pragma unroll
  for (int o=0;o<16;o++) acc[o]=0ull;
  #pragma unroll 1
  for (int jj=0;jj<128;jj+=4){
    ull h0=0ull,h1=0ull,h2=0ull,h3=0ull;
    #pragma unroll
    for (int c=0;c<48;c++){
      const ulonglong2* wp=(const ulonglong2*)(w2s + c*128 + jj);
      ulonglong2 wa=wp[0], wb=wp[1];
      ull yc=y[c];
      h0=fma2(yc,wa.x,h0); h1=fma2(yc,wa.y,h1);
      h2=fma2(yc,wb.x,h2); h3=fma2(yc,wb.y,h3);
    }
    h0=relu2(h0); h1=relu2(h1); h2=relu2(h2); h3=relu2(h3);
    #pragma unroll
    for (int q=0;q<4;q++){
      ull hv = (q==0)?h0 : (q==1)?h1 : (q==2)?h2 : h3;
      const ulonglong2* wp=(const ulonglong2*)(w3s + (jj+q)*16);
      #pragma unroll
      for (int o2=0;o2<8;o2++){
        ulonglong2 wv = wp[o2];
        acc[2*o2]   = fma2(hv, wv.x, acc[2*o2]);
        acc[2*o2+1] = fma2(hv, wv.y, acc[2*o2+1]);
      }
    }
  }

  float* u0p = uout + (size_t)(bp  )*16*HW + h*96 + w;
  float* u1p = uout + (size_t)(bp+4)*16*HW + h*96 + w;
  #pragma unroll
  for (int c=0;c<16;c++){
    float xa,xb,ua,ub;
    upk(y[3*c],xa,xb);
    upk(acc[c],ua,ub);
    u0p[c*HW] = xa + (((m0>>c)&1u)? ua : 0.f);
    u1p[c*HW] = xb + (((m1>>c)&1u)? ub : 0.f);
  }
}

__device__ __forceinline__ void load_weights(ull* w2s, ull* w3s,
    const float* __restrict__ w2g, const float* __restrict__ w3g, int tid)
{
  for (int idx=tid; idx<6144; idx+=256){     // w2 global: [j=128][c=48]
    int j=idx/48, c=idx-j*48; float v=w2g[idx]; w2s[c*128+j]=pk(v,v);
  }
  for (int idx=tid; idx<2048; idx+=256){     // w3 global: [o=16][j=128]
    int o=idx>>7, j=idx&127; float v=w3g[idx]; w3s[j*16+o]=pk(v,v);
  }
}

// ---------------- step 0: input x is already the state (no alive-mask) ----------------
__global__ __launch_bounds__(256,1) void ca_step0(const float* __restrict__ xin,
    float* __restrict__ uout,
    const float* __restrict__ w2g, const float* __restrict__ w3g,
    unsigned k0, unsigned k1)
{
  extern __shared__ ull sm[];
  ull* tile = sm;               // 5184
  ull* w2s  = sm + 5184;        // 6144
  ull* w3s  = w2s + 6144;       // 2048
  const int tid = threadIdx.x;
  const int bp  = blockIdx.z;
  const int x0p = blockIdx.x*16, y0p = blockIdx.y*16;
  const float* b0 = xin + (size_t)(bp  )*16*HW;
  const float* b1 = xin + (size_t)(bp+4)*16*HW;

  for (int idx=tid; idx<5184; idx+=256){
    int c = idx/324, r = idx-c*324, yy=r/18, xx=r-yy*18;
    int h = y0p+yy-1, w = x0p+xx-1;
    float v0=0.f, v1=0.f;
    if ((unsigned)h<96u && (unsigned)w<96u){ int off=c*HW+h*96+w; v0=b0[off]; v1=b1[off]; }
    tile[idx]=pk(v0,v1);
  }
  load_weights(w2s,w3s,w2g,w3g,tid);
  __syncthreads();
  const int tx = tid&15, ty = tid>>4;
  step_core(tile,w2s,w3s,uout,bp,y0p+ty,x0p+tx,tx,ty,k0,k1);
}

// ---------------- fused step t>=1: build x_t = alive-mask(u_{t-1}) in-block, ----------------
// write frames[t-1], then compute u_t.
__global__ __launch_bounds__(256,1) void ca_step_fused(
    const float* __restrict__ prevx,   // x_{t-1} (alpha source for pre-alive)
    const float* __restrict__ uprev,   // u_{t-1}
    float* __restrict__ uout,          // u_t
    float* __restrict__ frame_out,     // frames[t-1]
    const float* __restrict__ w2g, const float* __restrict__ w3g,
    unsigned k0, unsigned k1)
{
  extern __shared__ ull sm[];
  ull* tile = sm;               // 5184
  ull* w2s  = sm + 5184;        // 6144
  ull* w3s  = w2s + 6144;       // 2048
  ull* ap   = w3s + 2048;       // 400 : 20x20 alpha of prevx
  ull* au   = ap  + 400;        // 400 : 20x20 alpha of uprev
  ull* msk  = au  + 400;        // 324 : 18x18 alive mask (1.0/0.0 per lane)
  const int tid = threadIdx.x;
  const int bp  = blockIdx.z;
  const int x0p = blockIdx.x*16, y0p = blockIdx.y*16;

  // Phase A: 20x20 alpha halos (channel 3)
  const float* pa0 = prevx + (size_t)(bp*16+3)*HW;
  const float* pa1 = prevx + (size_t)((bp+4)*16+3)*HW;
  const float* ua0 = uprev + (size_t)(bp*16+3)*HW;
  const float* ua1 = uprev + (size_t)((bp+4)*16+3)*HW;
  for (int idx=tid; idx<400; idx+=256){
    int yy=idx/20, xx=idx-yy*20;
    int h=y0p+yy-2, w=x0p+xx-2;
    float p0=0.f,p1=0.f,q0=0.f,q1=0.f;
    if ((unsigned)h<96u && (unsigned)w<96u){
      int o=h*96+w; p0=pa0[o]; p1=pa1[o]; q0=ua0[o]; q1=ua1[o];
    }
    ap[idx]=pk(p0,p1); au[idx]=pk(q0,q1);
  }
  load_weights(w2s,w3s,w2g,w3g,tid);
  __syncthreads();

  // Phase B: 18x18 alive mask = (maxpool3(prev alpha)>.1) & (maxpool3(u alpha)>.1)
  for (int idx=tid; idx<324; idx+=256){
    int yy=idx/18, xx=idx-yy*18;            // center at (yy+1, xx+1) in 20x20
    float po0=-1e30f,po1=-1e30f,qo0=-1e30f,qo1=-1e30f;
    #pragma unroll
    for (int dy=0;dy<3;dy++){
      #pragma unroll
      for (int dx=0;dx<3;dx++){
        float a,b; upk(ap[(yy+dy)*20+xx+dx],a,b); po0=fmaxf(po0,a); po1=fmaxf(po1,b);
        float c,d; upk(au[(yy+dy)*20+xx+dx],c,d); qo0=fmaxf(qo0,c); qo1=fmaxf(qo1,d);
      }
    }
    float m0 = ((po0>0.1f)&&(qo0>0.1f))?1.f:0.f;
    float m1 = ((po1>0.1f)&&(qo1>0.1f))?1.f:0.f;
    msk[idx]=pk(m0,m1);
  }
  __syncthreads();

  // Phase C: tile = mask * u_prev over 18x18 halo; write interior to frames[t-1]
  const float* u0 = uprev + (size_t)(bp  )*16*HW;
  const float* u1 = uprev + (size_t)(bp+4)*16*HW;
  float* f0 = frame_out + (size_t)(bp  )*16*HW;
  float* f1 = frame_out + (size_t)(bp+4)*16*HW;
  for (int idx=tid; idx<5184; idx+=256){
    int c = idx/324, r = idx-c*324, yy=r/18, xx=r-yy*18;
    int h = y0p+yy-1, w = x0p+xx-1;
    ull v = 0ull;
    if ((unsigned)h<96u && (unsigned)w<96u){
      int off=c*HW+h*96+w;
      v = mul2(pk(u0[off],u1[off]), msk[r]);
      if (yy>=1 && yy<=16 && xx>=1 && xx<=16){
        float a,b; upk(v,a,b); f0[off]=a; f1[off]=b;
      }
    }
    tile[idx]=v;
  }
  __syncthreads();

  const int tx = tid&15, ty = tid>>4;
  step_core(tile,w2s,w3s,uout,bp,y0p+ty,x0p+tx,tx,ty,k0,k1);
}

// ---------------- trailing alive-mask for the final frame ----------------
__global__ __launch_bounds__(256,1) void ca_mask(const float* __restrict__ xin,
                                                 const float* __restrict__ u,
                                                 float* __restrict__ xout)
{
  int idx = blockIdx.x*256 + threadIdx.x;      // (b,h,w)
  int w = idx%96; int t1 = idx/96; int h = t1%96; int b = t1/96;
  const float* ao = xin + (size_t)(b*16+3)*HW;
  const float* an = u   + (size_t)(b*16+3)*HW;
  float mo=-1e30f, mn=-1e30f;
  #pragma unroll
  for (int dh=-1;dh<=1;dh++){
    int hh=h+dh; if((unsigned)hh>=96u) continue;
    #pragma unroll
    for (int dw=-1;dw<=1;dw++){
      int ww=w+dw; if((unsigned)ww>=96u) continue;
      int o=hh*96+ww;
      mo=fmaxf(mo,ao[o]); mn=fmaxf(mn,an[o]);
    }
  }
  float m = ((mo>0.1f)&&(mn>0.1f)) ? 1.0f : 0.0f;
  const float* up = u + (size_t)b*16*HW + h*96 + w;
  float* op = xout + (size_t)b*16*HW + h*96 + w;
  #pragma unroll
  for (int c=0;c<16;c++) op[c*HW] = m * up[c*HW];
}

// ---------------- host launcher ----------------
extern "C" void kernel_launch(void* const* d_in, const int* in_sizes, int n_in,
                              void* d_out, int out_size)
{
  const float* x=nullptr; const float* w2=nullptr; const float* w3=nullptr;
  for (int i=0;i<n_in;i++){
    if      (in_sizes[i]==N_ELEM) x =(const float*)d_in[i];
    else if (in_sizes[i]==6144)   w2=(const float*)d_in[i];
    else if (in_sizes[i]==2048)   w3=(const float*)d_in[i];
  }
  float* out=(float*)d_out;
  int T = out_size / N_ELEM;                  // 24

  float* U[2];
  cudaGetSymbolAddress((void**)&U[0], g_U);   // base of g_U[0]
  U[1] = U[0] + N_ELEM;

  size_t smem0 = (size_t)(5184+6144+2048)*sizeof(ull);            // 107008
  size_t smemF = smem0 + (size_t)(400+400+324)*sizeof(ull);       // 116000
  cudaFuncSetAttribute(ca_step0,      cudaFuncAttributeMaxDynamicSharedMemorySize, (int)smem0);
  cudaFuncSetAttribute(ca_step_fused, cudaFuncAttributeMaxDynamicSharedMemorySize, (int)smemF);

  // step 0
  {
    unsigned k0,k1; tf2x32(0u,42u, 0u,0u, k0,k1);
    ca_step0<<<dim3(6,6,4),256,smem0>>>(x, U[0], w2, w3, k0, k1);
  }
  // steps 1..T-1 (fused: materialize frames[t-1], compute u_t)
  for (int t=1;t<T;t++){
    unsigned k0,k1; tf2x32(0u,42u, 0u,(unsigned)t, k0,k1);
    const float* prevx = (t==1) ? x : out + (size_t)(t-2)*N_ELEM;
    ca_step_fused<<<dim3(6,6,4),256,smemF>>>(prevx, U[(t-1)&1], U[t&1],
                                             out + (size_t)(t-1)*N_ELEM, w2, w3, k0, k1);
  }
  // final frame
  {
    const float* prevx = (T>=2) ? out + (size_t)(T-2)*N_ELEM : x;
    ca_mask<<<288,256>>>(prevx, U[(T-1)&1], out + (size_t)(T-1)*N_ELEM);
  }
}

// round 7
// speedup vs baseline: 1.0933x; 1.0933x over previous
#include <cuda_runtime.h>
#include <cstdint>

// Problem constants (fixed shapes: x = (8,16,96,96) f32, 24 steps)
#define N_ELEM 1179648   // 8*16*96*96
#define HALF   589824    // N_ELEM/2  (== 4 batches * 16 ch * 96*96)
#define HW     9216      // 96*96

typedef unsigned long long ull;

// ---------------- packed f32x2 helpers (Blackwell FFMA2 path) ----------------
__device__ __forceinline__ ull pk(float lo, float hi){ ull r; asm("mov.b64 %0,{%1,%2};":"=l"(r):"f"(lo),"f"(hi)); return r; }
__device__ __forceinline__ void upk(ull v, float&lo, float&hi){ asm("mov.b64 {%0,%1},%2;":"=f"(lo),"=f"(hi):"l"(v)); }
__device__ __forceinline__ ull fma2(ull a, ull b, ull c){ ull d; asm("fma.rn.f32x2 %0,%1,%2,%3;":"=l"(d):"l"(a),"l"(b),"l"(c)); return d; }
__device__ __forceinline__ ull add2(ull a, ull b){ ull d; asm("add.rn.f32x2 %0,%1,%2;":"=l"(d):"l"(a),"l"(b)); return d; }
__device__ __forceinline__ ull mul2(ull a, ull b){ ull d; asm("mul.rn.f32x2 %0,%1,%2;":"=l"(d):"l"(a),"l"(b)); return d; }
__device__ __forceinline__ ull sub2(ull a, ull b){ return add2(a, b ^ 0x8000000080000000ULL); }
__device__ __forceinline__ ull relu2(ull v){ float lo,hi; upk(v,lo,hi); return pk(fmaxf(lo,0.f), fmaxf(hi,0.f)); }

// ---------------- Threefry-2x32-20 (exact JAX PRNG, partitionable mode) ----------------
__host__ __device__ __forceinline__ unsigned rotl32(unsigned x, int r){
#ifdef __CUDA_ARCH__
  return __funnelshift_l(x,x,r);
#else
  return (x<<r)|(x>>(32-r));
#endif
}
__host__ __device__ __forceinline__ void tf2x32(unsigned k0,unsigned k1,unsigned x0,unsigned x1,
                                                unsigned&o0,unsigned&o1){
  unsigned k2 = k0^k1^0x1BD11BDAu;
  x0+=k0; x1+=k1;
#define TFR(a) {x0+=x1; x1=rotl32(x1,(a)); x1^=x0;}
  TFR(13)TFR(15)TFR(26)TFR(6)   x0+=k1; x1+=k2+1u;
  TFR(17)TFR(29)TFR(16)TFR(24)  x0+=k2; x1+=k0+2u;
  TFR(13)TFR(15)TFR(26)TFR(6)   x0+=k0; x1+=k1+3u;
  TFR(17)TFR(29)TFR(16)TFR(24)  x0+=k1; x1+=k2+4u;
  TFR(13)TFR(15)TFR(26)TFR(6)   x0+=k2; x1+=k0+5u;
#undef TFR
  o0=x0; o1=x1;
}
__device__ __forceinline__ unsigned rbits32(unsigned k0, unsigned k1, unsigned i){
  unsigned o0,o1; tf2x32(k0,k1, 0u, i, o0,o1); return o0^o1;
}

// scratch: pre-mask updated state u = x + mask*update(x)
__device__ float g_U[N_ELEM];

// ---------------- Step kernel: perception + MLP + stochastic update ----------------
// Grid (6,6,4): 16x16 spatial tile, z = batch pair (b, b+4). Each thread = 1 pixel,
// two batches packed in f32x2 lanes. Weights pre-duplicated (w,w) in smem so each
// FFMA2 operand is one shared load.
__global__ __launch_bounds__(256,1) void ca_step(const float* __restrict__ xin,
    float* __restrict__ uout,
    const float* __restrict__ w2g, const float* __restrict__ w3g,
    unsigned k0, unsigned k1)
{
  extern __shared__ ull sm[];
  ull* tile = sm;               // [16ch][18][18] packed pairs : 5184
  ull* w2s  = sm + 5184;        // [c=48][j=128] duplicated    : 6144
  ull* w3s  = w2s + 6144;       // [j=128][o=16] duplicated    : 2048
  const int tid = threadIdx.x;
  const int bp  = blockIdx.z;                 // 0..3 -> batches bp, bp+4
  const int x0p = blockIdx.x*16, y0p = blockIdx.y*16;
  const float* b0 = xin + (size_t)(bp  )*16*HW;
  const float* b1 = xin + (size_t)(bp+4)*16*HW;

  for (int idx=tid; idx<5184; idx+=256){
    int c = idx/324, r = idx-c*324, yy=r/18, xx=r-yy*18;
    int h = y0p+yy-1, w = x0p+xx-1;
    float v0=0.f, v1=0.f;
    if ((unsigned)h<96u && (unsigned)w<96u){ int off=c*HW+h*96+w; v0=b0[off]; v1=b1[off]; }
    tile[idx]=pk(v0,v1);
  }
  for (int idx=tid; idx<6144; idx+=256){     // w2 global: [j=128][c=48]
    int j=idx/48, c=idx-j*48; float v=w2g[idx]; w2s[c*128+j]=pk(v,v);
  }
  for (int idx=tid; idx<2048; idx+=256){     // w3 global: [o=16][j=128]
    int o=idx>>7, j=idx&127; float v=w3g[idx]; w3s[j*16+o]=pk(v,v);
  }
  __syncthreads();

  const int tx = tid&15, ty = tid>>4;
  const int h = y0p+ty, w = x0p+tx;

  // perception: y[3c]=identity, y[3c+1]=sobel-x, y[3c+2]=sobel-y (cross-correlation, /8)
  ull y[48];
  const ull EIGHTH = pk(0.125f,0.125f);
  #pragma unroll
  for (int c=0;c<16;c++){
    const ull* t = tile + c*324 + (ty+1)*18 + (tx+1);
    ull a=t[-19], bb=t[-18], cc=t[-17], d=t[-1], e=t[0], f=t[1], g=t[17], hh=t[18], ii=t[19];
    y[3*c]=e;
    ull sx = sub2(f,d);
    y[3*c+1]=mul2(add2(add2(sub2(cc,a),sub2(ii,g)),add2(sx,sx)),EIGHTH);
    ull sy = sub2(hh,bb);
    y[3*c+2]=mul2(add2(add2(sub2(g,a),sub2(ii,cc)),add2(sy,sy)),EIGHTH);
  }

  // MLP (hid = relu(W2 y), out = W3 hid) with the stochastic-mask PRNG
  // interleaved: the 16 j-blocks exactly host the 16 channels' threefry pairs,
  // whose ALU work fills FMA/LDS stall slots.
  unsigned m0=0u, m1=0u;
  ull acc[16];
  #pragma unroll
  for (int o=0;o<16;o++) acc[o]=0ull;
  const unsigned ibase = (unsigned)(bp*16*HW + h*96 + w);

  #pragma unroll 1
  for (int it=0; it<16; it++){
    const int jj = it*8;

    // PRNG for channel `it` (both batch lanes); independent of the FMA stream
    unsigned i0 = ibase + (unsigned)(it*HW);
    unsigned r0 = rbits32(k0,k1, i0);
    unsigned r1 = rbits32(k0,k1, i0+(unsigned)HALF);
    float u0=__uint_as_float((r0>>9)|0x3f800000u)-1.0f;
    float u1=__uint_as_float((r1>>9)|0x3f800000u)-1.0f;
    m0 |= (u0>0.5f)?(1u<<it):0u;
    m1 |= (u1>0.5f)?(1u<<it):0u;

    // 8-wide hidden block: 4 LDS.128 + 16 fma2 per c -> self-hiding LDS latency
    ull hh[8];
    #pragma unroll
    for (int q=0;q<8;q++) hh[q]=0ull;
    #pragma unroll
    for (int c=0;c<48;c++){
      const ulonglong2* wp=(const ulonglong2*)(w2s + c*128 + jj);
      ulonglong2 wa=wp[0], wb=wp[1], wc=wp[2], wd=wp[3];
      ull yc=y[c];
      hh[0]=fma2(yc,wa.x,hh[0]); hh[1]=fma2(yc,wa.y,hh[1]);
      hh[2]=fma2(yc,wb.x,hh[2]); hh[3]=fma2(yc,wb.y,hh[3]);
      hh[4]=fma2(yc,wc.x,hh[4]); hh[5]=fma2(yc,wc.y,hh[5]);
      hh[6]=fma2(yc,wd.x,hh[6]); hh[7]=fma2(yc,wd.y,hh[7]);
    }
    #pragma unroll
    for (int q=0;q<8;q++) hh[q]=relu2(hh[q]);
    #pragma unroll
    for (int q=0;q<8;q++){
      const ulonglong2* wp=(const ulonglong2*)(w3s + (jj+q)*16);
      ull hv = hh[q];
      #pragma unroll
      for (int o2=0;o2<8;o2++){
        ulonglong2 wv = wp[o2];
        acc[2*o2]   = fma2(hv, wv.x, acc[2*o2]);
        acc[2*o2+1] = fma2(hv, wv.y, acc[2*o2+1]);
      }
    }
  }

  // u = x + mask*update (pre-alive-mask state) -> scratch
  float* u0p = uout + (size_t)(bp  )*16*HW + h*96 + w;
  float* u1p = uout + (size_t)(bp+4)*16*HW + h*96 + w;
  #pragma unroll
  for (int c=0;c<16;c++){
    float xa,xb,ua,ub;
    upk(y[3*c],xa,xb);
    upk(acc[c],ua,ub);
    u0p[c*HW] = xa + (((m0>>c)&1u)? ua : 0.f);
    u1p[c*HW] = xb + (((m1>>c)&1u)? ub : 0.f);
  }
}

// ---------------- Alive-mask kernel: frames[t] = u * (alive_pre & alive_post) ----------------
// 2x parallelism: thread handles 8 channels; half-split is the outer index so
// warps stay coalesced (32 consecutive w, same channel).
__global__ __launch_bounds__(256,1) void ca_mask(const float* __restrict__ xin,
                                                 const float* __restrict__ u,
                                                 float* __restrict__ xout)
{
  int idx = blockIdx.x*256 + threadIdx.x;      // 0..147455
  int p    = idx % 73728;                      // (b,h,w)
  int half = idx / 73728;                      // 0/1 -> channels 0-7 / 8-15
  int w = p%96; int t1 = p/96; int h = t1%96; int b = t1/96;
  const float* ao = xin + (size_t)(b*16+3)*HW;
  const float* an = u   + (size_t)(b*16+3)*HW;
  float mo=-1e30f, mn=-1e30f;
  #pragma unroll
  for (int dh=-1;dh<=1;dh++){
    int hh=h+dh; if((unsigned)hh>=96u) continue;
    #pragma unroll
    for (int dw=-1;dw<=1;dw++){
      int ww=w+dw; if((unsigned)ww>=96u) continue;
      int o=hh*96+ww;
      mo=fmaxf(mo,ao[o]); mn=fmaxf(mn,an[o]);
    }
  }
  float m = ((mo>0.1f)&&(mn>0.1f)) ? 1.0f : 0.0f;
  const float* up = u    + (size_t)(b*16+half*8)*HW + h*96 + w;
  float* op       = xout + (size_t)(b*16+half*8)*HW + h*96 + w;
  #pragma unroll
  for (int c=0;c<8;c++) op[c*HW] = m * up[c*HW];
}

// ---------------- host launcher ----------------
extern "C" void kernel_launch(void* const* d_in, const int* in_sizes, int n_in,
                              void* d_out, int out_size)
{
  const float* x=nullptr; const float* w2=nullptr; const float* w3=nullptr;
  for (int i=0;i<n_in;i++){
    if      (in_sizes[i]==N_ELEM) x =(const float*)d_in[i];
    else if (in_sizes[i]==6144)   w2=(const float*)d_in[i];
    else if (in_sizes[i]==2048)   w3=(const float*)d_in[i];
  }
  float* out=(float*)d_out;
  int T = out_size / N_ELEM;                  // 24

  float* U;
  cudaGetSymbolAddress((void**)&U, g_U);

  size_t smem = (size_t)(5184+6144+2048)*sizeof(ull);   // 107008 B
  cudaFuncSetAttribute(ca_step, cudaFuncAttributeMaxDynamicSharedMemorySize, (int)smem);

  const float* xin = x;
  for (int t=0;t<T;t++){
    // key_t = threefry(base key (0,42), counter (hi=0, lo=t))  [partitionable split]
    unsigned k0,k1; tf2x32(0u,42u, 0u,(unsigned)t, k0,k1);
    ca_step<<<dim3(6,6,4),256,smem>>>(xin, U, w2, w3, k0, k1);
    ca_mask<<<576,256>>>(xin, U, out + (size_t)t*N_ELEM);
    xin = out + (size_t)t*N_ELEM;
  }
}